// round 13
// baseline (speedup 1.0000x reference)
#include <cuda_runtime.h>

// RNAPocketEncoderV3: LayerNorm on first 32 feats + global-mean norm-rescale of
// 16 vec(3) + 8 ten(5) channels. Two passes (global mean couples all rows).
//
// Row = 120 floats = 30 float4.
//   [0,32)   scalar -> layernorm (lanes 0-7)
//   [32,80)  16 vec(3)  -> channels 0..15   (lanes 8..19)
//   [80,120) 8 ten(5)   -> channels 16..23  (lanes 20..29)
//
// Both passes walk rows ASCENDING (forward streaming is fastest; R11 showed
// descending loses ~5us). k_main is software-pipelined: next group's loads are
// issued before the current group's math+stores.

#define NCH 24
#define EPS_LN   1e-5f
#define EPS_NORM 1e-6f
#define EPS2     1e-12f
#define RB 1184
#define MB 4096
#define FULL 0xffffffffu

__device__ float g_partials[RB * NCH];
__device__ float g_mean[NCH];

__device__ __forceinline__ int chan(int e) {   // e in [32,120)
    return (e < 80) ? ((e - 32) / 3) : (16 + (e - 80) / 5);
}

// routing for destination lane c in [0,24): channel c = contrib1 + contrib2
//   contrib1 = (c%4==0 ? sA : sB) from lane r1(c); contrib2 = sA from lane r2(c)
//   (r2=0 -> lane0, whose partials are 0)
__device__ __forceinline__ void routing(int lane, int& r1, int& r2, bool& r1A) {
    r1 = 0; r2 = 0;
    if (lane < 16) {
        r1 = 8 + (3 * lane) / 4;
        int m = lane & 3;
        r2 = (m == 1 || m == 2) ? (r1 + 1) : 0;
    } else if (lane < 24) {
        int j = lane - 16;
        r1 = 20 + (5 * j) / 4;
        r2 = r1 + 1;
    }
    r1A = ((lane & 3) == 0);
}

__device__ __forceinline__ void partials(const float4& v, bool b1, bool b2, bool b3,
                                         float& sA, float& sB) {
    float q0 = v.x * v.x, q1 = v.y * v.y, q2 = v.z * v.z, q3 = v.w * v.w;
    sA = q0; sB = 0.f;
    if (b1) sA += q1; else sB += q1;
    if (b2) sA += q2; else sB += q2;
    if (b3) sA += q3; else sB += q3;
}

__device__ __forceinline__ float chan_sum(float sA, float sB, int r1, int r2, bool r1A) {
    float a1 = __shfl_sync(FULL, sA, r1);
    float b1 = __shfl_sync(FULL, sB, r1);
    float a2 = __shfl_sync(FULL, sA, r2);
    return (r1A ? a1 : b1) + a2;
}

__device__ __forceinline__ float clamped_norm(float n2) {
    return (n2 > EPS2) ? n2 * rsqrtf(n2) : EPS_NORM;
}

// -------- Pass 1: per-channel sum of clamped norms (block partials) --------
__global__ __launch_bounds__(256)
void k_reduce(const float4* __restrict__ x, int N) {
    __shared__ float warp_acc[8][NCH];
    const int tid  = threadIdx.x;
    const int wid  = tid >> 5;
    const int lane = tid & 31;

    const int gwarp  = blockIdx.x * 8 + wid;
    const int stride = gridDim.x * 8;
    const bool ldlane = (lane >= 8 && lane < 30);

    bool b1 = true, b2 = true, b3 = true;
    if (ldlane) {
        int e0 = lane * 4, cA = chan(e0);
        b1 = (chan(e0 + 1) == cA); b2 = (chan(e0 + 2) == cA); b3 = (chan(e0 + 3) == cA);
    }
    int r1, r2; bool r1A;
    routing(lane, r1, r2, r1A);

    float acc = 0.f;
    int row = gwarp;
    for (; row + 3 * stride < N; row += 4 * stride) {
        float4 v0, v1, v2, v3;
        v0 = v1 = v2 = v3 = make_float4(0.f, 0.f, 0.f, 0.f);
        if (ldlane) {
            v0 = __ldg(&x[(long long)row * 30 + lane]);
            v1 = __ldg(&x[(long long)(row + stride) * 30 + lane]);
            v2 = __ldg(&x[(long long)(row + 2 * stride) * 30 + lane]);
            v3 = __ldg(&x[(long long)(row + 3 * stride) * 30 + lane]);
        }
        float sA0, sB0, sA1, sB1, sA2, sB2, sA3, sB3;
        partials(v0, b1, b2, b3, sA0, sB0);
        partials(v1, b1, b2, b3, sA1, sB1);
        partials(v2, b1, b2, b3, sA2, sB2);
        partials(v3, b1, b2, b3, sA3, sB3);
        float n0 = chan_sum(sA0, sB0, r1, r2, r1A);
        float n1 = chan_sum(sA1, sB1, r1, r2, r1A);
        float n2 = chan_sum(sA2, sB2, r1, r2, r1A);
        float n3 = chan_sum(sA3, sB3, r1, r2, r1A);
        acc += clamped_norm(n0) + clamped_norm(n1) + clamped_norm(n2) + clamped_norm(n3);
    }
    for (; row < N; row += stride) {
        float4 v0 = make_float4(0.f, 0.f, 0.f, 0.f);
        if (ldlane) v0 = __ldg(&x[(long long)row * 30 + lane]);
        float sA, sB;
        partials(v0, b1, b2, b3, sA, sB);
        float n = chan_sum(sA, sB, r1, r2, r1A);
        acc += clamped_norm(n);
    }

    if (lane < NCH) warp_acc[wid][lane] = acc;
    __syncthreads();
    if (tid < NCH) {
        float s = 0.f;
        #pragma unroll
        for (int w = 0; w < 8; w++) s += warp_acc[w][tid];   // fixed order: deterministic
        g_partials[blockIdx.x * NCH + tid] = s;
    }
}

// -------- Pass 1b: finalize means --------
__global__ void k_finalize(int nblocks, float invN) {
    const int wid  = threadIdx.x >> 5;
    const int lane = threadIdx.x & 31;
    if (wid < NCH) {
        float s = 0.f;
        for (int i = lane; i < nblocks; i += 32) s += g_partials[i * NCH + wid];
        #pragma unroll
        for (int o = 16; o; o >>= 1) s += __shfl_xor_sync(FULL, s, o);
        if (lane == 0) g_mean[wid] = s * invN;
    }
}

// -------- Pass 2: layernorm + rescale (pipelined 4-row groups) --------
__device__ __forceinline__ float4 process_row(
    const float4& v, bool sclane, bool vclane,
    const float4& wv, const float4& bv, float meanc,
    bool b1, bool b2, int cA, int c3,
    int r1, int r2, bool r1A, bool b3)
{
    float s = 0.f, sq = 0.f;
    if (sclane) {
        s  = v.x + v.y + v.z + v.w;
        sq = v.x * v.x + v.y * v.y + v.z * v.z + v.w * v.w;
    }
    #pragma unroll
    for (int o = 4; o; o >>= 1) {
        s  += __shfl_xor_sync(FULL, s,  o);
        sq += __shfl_xor_sync(FULL, sq, o);
    }

    float sA = 0.f, sB = 0.f;
    if (vclane) partials(v, b1, b2, b3, sA, sB);
    float n2 = chan_sum(sA, sB, r1, r2, r1A);
    float scale = (n2 > EPS2) ? meanc * rsqrtf(n2) : meanc * (1.f / EPS_NORM);

    float sc_lo = __shfl_sync(FULL, scale, cA);
    float sc_hi = __shfl_sync(FULL, scale, c3);

    float4 o4 = make_float4(0.f, 0.f, 0.f, 0.f);
    if (sclane) {
        float mu  = s * (1.f / 32.f);
        float var = sq * (1.f / 32.f) - mu * mu;
        float r   = rsqrtf(var + EPS_LN);
        o4.x = (v.x - mu) * r * wv.x + bv.x;
        o4.y = (v.y - mu) * r * wv.y + bv.y;
        o4.z = (v.z - mu) * r * wv.z + bv.z;
        o4.w = (v.w - mu) * r * wv.w + bv.w;
    } else if (vclane) {
        o4.x = v.x * sc_lo;
        o4.y = v.y * (b1 ? sc_lo : sc_hi);
        o4.z = v.z * (b2 ? sc_lo : sc_hi);
        o4.w = v.w * sc_hi;
    }
    return o4;
}

__global__ __launch_bounds__(256)
void k_main(const float4* __restrict__ x,
            const float* __restrict__ w, const float* __restrict__ b,
            float4* __restrict__ out, int N) {
    const int tid  = threadIdx.x;
    const int wid  = tid >> 5;
    const int lane = tid & 31;

    const int gwarp  = blockIdx.x * 8 + wid;
    const int stride = gridDim.x * 8;
    const bool sclane = (lane < 8);
    const bool vclane = (lane >= 8 && lane < 30);
    const bool io     = (lane < 30);

    float4 wv = make_float4(0.f, 0.f, 0.f, 0.f), bv = wv;
    if (sclane) {
        wv = __ldg(&((const float4*)w)[lane]);
        bv = __ldg(&((const float4*)b)[lane]);
    }
    const float meanc = (lane < NCH) ? g_mean[lane] : 0.f;

    int cA = 0, c3 = 0; bool b1 = true, b2 = true, b3 = true;
    if (vclane) {
        int e0 = lane * 4;
        cA = chan(e0); c3 = chan(e0 + 3);
        b1 = (chan(e0 + 1) == cA); b2 = (chan(e0 + 2) == cA); b3 = (c3 == cA);
    }
    int r1, r2; bool r1A;
    routing(lane, r1, r2, r1A);

    int row = gwarp;
    float4 a0, a1, a2, a3;
    a0 = a1 = a2 = a3 = make_float4(0.f, 0.f, 0.f, 0.f);
    bool have = (row + 3 * stride < N);
    if (have && io) {
        a0 = __ldg(&x[(long long)row * 30 + lane]);
        a1 = __ldg(&x[(long long)(row + stride) * 30 + lane]);
        a2 = __ldg(&x[(long long)(row + 2 * stride) * 30 + lane]);
        a3 = __ldg(&x[(long long)(row + 3 * stride) * 30 + lane]);
    }
    while (have) {
        const int nrow = row + 4 * stride;
        const bool nexth = (nrow + 3 * stride < N);
        float4 c0, c1, c2, c3f;
        c0 = c1 = c2 = c3f = make_float4(0.f, 0.f, 0.f, 0.f);
        if (nexth && io) {
            c0 = __ldg(&x[(long long)nrow * 30 + lane]);
            c1 = __ldg(&x[(long long)(nrow + stride) * 30 + lane]);
            c2 = __ldg(&x[(long long)(nrow + 2 * stride) * 30 + lane]);
            c3f = __ldg(&x[(long long)(nrow + 3 * stride) * 30 + lane]);
        }
        float4 o0 = process_row(a0, sclane, vclane, wv, bv, meanc, b1, b2, cA, c3, r1, r2, r1A, b3);
        float4 o1 = process_row(a1, sclane, vclane, wv, bv, meanc, b1, b2, cA, c3, r1, r2, r1A, b3);
        float4 o2 = process_row(a2, sclane, vclane, wv, bv, meanc, b1, b2, cA, c3, r1, r2, r1A, b3);
        float4 o3 = process_row(a3, sclane, vclane, wv, bv, meanc, b1, b2, cA, c3, r1, r2, r1A, b3);
        if (io) {
            __stcs(&out[(long long)row * 30 + lane], o0);
            __stcs(&out[(long long)(row + stride) * 30 + lane], o1);
            __stcs(&out[(long long)(row + 2 * stride) * 30 + lane], o2);
            __stcs(&out[(long long)(row + 3 * stride) * 30 + lane], o3);
        }
        a0 = c0; a1 = c1; a2 = c2; a3 = c3f;
        row = nrow;
        have = nexth;
    }
    for (; row < N; row += stride) {
        float4 v0 = make_float4(0.f, 0.f, 0.f, 0.f);
        if (io) v0 = __ldg(&x[(long long)row * 30 + lane]);
        float4 o0 = process_row(v0, sclane, vclane, wv, bv, meanc, b1, b2, cA, c3, r1, r2, r1A, b3);
        if (io) __stcs(&out[(long long)row * 30 + lane], o0);
    }
}

extern "C" void kernel_launch(void* const* d_in, const int* in_sizes, int n_in,
                              void* d_out, int out_size) {
    const float* x = (const float*)d_in[0];
    const float* w = (const float*)d_in[1];
    const float* b = (const float*)d_in[2];
    float* out = (float*)d_out;
    const int N = in_sizes[0] / 120;

    k_reduce<<<RB, 256>>>((const float4*)x, N);
    k_finalize<<<1, 768>>>(RB, 1.0f / (float)N);
    k_main<<<MB, 256>>>((const float4*)x, w, b, (float4*)out, N);
}

// round 15
// speedup vs baseline: 1.1111x; 1.1111x over previous
#include <cuda_runtime.h>

// RNAPocketEncoderV3: LayerNorm on first 32 feats + global-mean norm-rescale of
// 16 vec(3) + 8 ten(5) channels. Two passes (global mean couples all rows).
//
// Row = 120 floats = 30 float4.
//   [0,32)   scalar -> layernorm (lanes 0-7)
//   [32,80)  16 vec(3)  -> channels 0..15   (lanes 8..19)
//   [80,120) 8 ten(5)   -> channels 16..23  (lanes 20..29)
//
// Both passes walk rows ASCENDING (R11: descending loses). No hand pipelining
// (R13: loses). k_main: straight 8x unroll, loads batched first.

#define NCH 24
#define EPS_LN   1e-5f
#define EPS_NORM 1e-6f
#define EPS2     1e-12f
#define RB 1184
#define MB 4096
#define FULL 0xffffffffu

__device__ float g_partials[RB * NCH];
__device__ float g_mean[NCH];

__device__ __forceinline__ int chan(int e) {   // e in [32,120)
    return (e < 80) ? ((e - 32) / 3) : (16 + (e - 80) / 5);
}

// routing for destination lane c in [0,24): channel c = contrib1 + contrib2
//   contrib1 = (c%4==0 ? sA : sB) from lane r1(c); contrib2 = sA from lane r2(c)
//   (r2=0 -> lane0, whose partials are 0)
__device__ __forceinline__ void routing(int lane, int& r1, int& r2, bool& r1A) {
    r1 = 0; r2 = 0;
    if (lane < 16) {
        r1 = 8 + (3 * lane) / 4;
        int m = lane & 3;
        r2 = (m == 1 || m == 2) ? (r1 + 1) : 0;
    } else if (lane < 24) {
        int j = lane - 16;
        r1 = 20 + (5 * j) / 4;
        r2 = r1 + 1;
    }
    r1A = ((lane & 3) == 0);
}

__device__ __forceinline__ void partials(const float4& v, bool b1, bool b2, bool b3,
                                         float& sA, float& sB) {
    float q0 = v.x * v.x, q1 = v.y * v.y, q2 = v.z * v.z, q3 = v.w * v.w;
    sA = q0; sB = 0.f;
    if (b1) sA += q1; else sB += q1;
    if (b2) sA += q2; else sB += q2;
    if (b3) sA += q3; else sB += q3;
}

__device__ __forceinline__ float chan_sum(float sA, float sB, int r1, int r2, bool r1A) {
    float a1 = __shfl_sync(FULL, sA, r1);
    float b1 = __shfl_sync(FULL, sB, r1);
    float a2 = __shfl_sync(FULL, sA, r2);
    return (r1A ? a1 : b1) + a2;
}

__device__ __forceinline__ float clamped_norm(float n2) {
    return (n2 > EPS2) ? n2 * rsqrtf(n2) : EPS_NORM;
}

__device__ __forceinline__ float4 ldcs4(const float4* p) { return __ldcs(p); }

// -------- Pass 1: per-channel sum of clamped norms (block partials) --------
__global__ __launch_bounds__(256)
void k_reduce(const float4* __restrict__ x, int N) {
    __shared__ float warp_acc[8][NCH];
    const int tid  = threadIdx.x;
    const int wid  = tid >> 5;
    const int lane = tid & 31;

    const int gwarp  = blockIdx.x * 8 + wid;
    const int stride = gridDim.x * 8;
    const bool ldlane = (lane >= 8 && lane < 30);

    bool b1 = true, b2 = true, b3 = true;
    if (ldlane) {
        int e0 = lane * 4, cA = chan(e0);
        b1 = (chan(e0 + 1) == cA); b2 = (chan(e0 + 2) == cA); b3 = (chan(e0 + 3) == cA);
    }
    int r1, r2; bool r1A;
    routing(lane, r1, r2, r1A);

    float acc = 0.f;
    int row = gwarp;
    for (; row + 3 * stride < N; row += 4 * stride) {
        float4 v0, v1, v2, v3;
        v0 = v1 = v2 = v3 = make_float4(0.f, 0.f, 0.f, 0.f);
        if (ldlane) {
            v0 = ldcs4(&x[(long long)row * 30 + lane]);
            v1 = ldcs4(&x[(long long)(row + stride) * 30 + lane]);
            v2 = ldcs4(&x[(long long)(row + 2 * stride) * 30 + lane]);
            v3 = ldcs4(&x[(long long)(row + 3 * stride) * 30 + lane]);
        }
        float sA0, sB0, sA1, sB1, sA2, sB2, sA3, sB3;
        partials(v0, b1, b2, b3, sA0, sB0);
        partials(v1, b1, b2, b3, sA1, sB1);
        partials(v2, b1, b2, b3, sA2, sB2);
        partials(v3, b1, b2, b3, sA3, sB3);
        float n0 = chan_sum(sA0, sB0, r1, r2, r1A);
        float n1 = chan_sum(sA1, sB1, r1, r2, r1A);
        float n2 = chan_sum(sA2, sB2, r1, r2, r1A);
        float n3 = chan_sum(sA3, sB3, r1, r2, r1A);
        acc += clamped_norm(n0) + clamped_norm(n1) + clamped_norm(n2) + clamped_norm(n3);
    }
    for (; row < N; row += stride) {
        float4 v0 = make_float4(0.f, 0.f, 0.f, 0.f);
        if (ldlane) v0 = ldcs4(&x[(long long)row * 30 + lane]);
        float sA, sB;
        partials(v0, b1, b2, b3, sA, sB);
        float n = chan_sum(sA, sB, r1, r2, r1A);
        acc += clamped_norm(n);
    }

    if (lane < NCH) warp_acc[wid][lane] = acc;
    __syncthreads();
    if (tid < NCH) {
        float s = 0.f;
        #pragma unroll
        for (int w = 0; w < 8; w++) s += warp_acc[w][tid];   // fixed order: deterministic
        g_partials[blockIdx.x * NCH + tid] = s;
    }
}

// -------- Pass 1b: finalize means --------
__global__ void k_finalize(int nblocks, float invN) {
    const int wid  = threadIdx.x >> 5;
    const int lane = threadIdx.x & 31;
    if (wid < NCH) {
        float s = 0.f;
        for (int i = lane; i < nblocks; i += 32) s += g_partials[i * NCH + wid];
        #pragma unroll
        for (int o = 16; o; o >>= 1) s += __shfl_xor_sync(FULL, s, o);
        if (lane == 0) g_mean[wid] = s * invN;
    }
}

// -------- Pass 2: layernorm + rescale (straight 8x unroll) --------
__device__ __forceinline__ float4 process_row(
    const float4& v, bool sclane, bool vclane,
    const float4& wv, const float4& bv, float meanc,
    bool b1, bool b2, int cA, int c3,
    int r1, int r2, bool r1A, bool b3)
{
    float s = 0.f, sq = 0.f;
    if (sclane) {
        s  = v.x + v.y + v.z + v.w;
        sq = v.x * v.x + v.y * v.y + v.z * v.z + v.w * v.w;
    }
    #pragma unroll
    for (int o = 4; o; o >>= 1) {
        s  += __shfl_xor_sync(FULL, s,  o);
        sq += __shfl_xor_sync(FULL, sq, o);
    }

    float sA = 0.f, sB = 0.f;
    if (vclane) partials(v, b1, b2, b3, sA, sB);
    float n2 = chan_sum(sA, sB, r1, r2, r1A);
    float scale = (n2 > EPS2) ? meanc * rsqrtf(n2) : meanc * (1.f / EPS_NORM);

    float sc_lo = __shfl_sync(FULL, scale, cA);
    float sc_hi = __shfl_sync(FULL, scale, c3);

    float4 o4 = make_float4(0.f, 0.f, 0.f, 0.f);
    if (sclane) {
        float mu  = s * (1.f / 32.f);
        float var = sq * (1.f / 32.f) - mu * mu;
        float r   = rsqrtf(var + EPS_LN);
        o4.x = (v.x - mu) * r * wv.x + bv.x;
        o4.y = (v.y - mu) * r * wv.y + bv.y;
        o4.z = (v.z - mu) * r * wv.z + bv.z;
        o4.w = (v.w - mu) * r * wv.w + bv.w;
    } else if (vclane) {
        o4.x = v.x * sc_lo;
        o4.y = v.y * (b1 ? sc_lo : sc_hi);
        o4.z = v.z * (b2 ? sc_lo : sc_hi);
        o4.w = v.w * sc_hi;
    }
    return o4;
}

__global__ __launch_bounds__(256)
void k_main(const float4* __restrict__ x,
            const float* __restrict__ w, const float* __restrict__ b,
            float4* __restrict__ out, int N) {
    const int tid  = threadIdx.x;
    const int wid  = tid >> 5;
    const int lane = tid & 31;

    const int gwarp  = blockIdx.x * 8 + wid;
    const int stride = gridDim.x * 8;
    const bool sclane = (lane < 8);
    const bool vclane = (lane >= 8 && lane < 30);
    const bool io     = (lane < 30);

    float4 wv = make_float4(0.f, 0.f, 0.f, 0.f), bv = wv;
    if (sclane) {
        wv = __ldg(&((const float4*)w)[lane]);
        bv = __ldg(&((const float4*)b)[lane]);
    }
    const float meanc = (lane < NCH) ? g_mean[lane] : 0.f;

    int cA = 0, c3 = 0; bool b1 = true, b2 = true, b3 = true;
    if (vclane) {
        int e0 = lane * 4;
        cA = chan(e0); c3 = chan(e0 + 3);
        b1 = (chan(e0 + 1) == cA); b2 = (chan(e0 + 2) == cA); b3 = (c3 == cA);
    }
    int r1, r2; bool r1A;
    routing(lane, r1, r2, r1A);

    int row = gwarp;
    for (; row + 7 * stride < N; row += 8 * stride) {
        float4 v0, v1, v2, v3, v4, v5, v6, v7;
        v0 = v1 = v2 = v3 = v4 = v5 = v6 = v7 = make_float4(0.f, 0.f, 0.f, 0.f);
        if (io) {
            v0 = ldcs4(&x[(long long)row * 30 + lane]);
            v1 = ldcs4(&x[(long long)(row + stride) * 30 + lane]);
            v2 = ldcs4(&x[(long long)(row + 2 * stride) * 30 + lane]);
            v3 = ldcs4(&x[(long long)(row + 3 * stride) * 30 + lane]);
            v4 = ldcs4(&x[(long long)(row + 4 * stride) * 30 + lane]);
            v5 = ldcs4(&x[(long long)(row + 5 * stride) * 30 + lane]);
            v6 = ldcs4(&x[(long long)(row + 6 * stride) * 30 + lane]);
            v7 = ldcs4(&x[(long long)(row + 7 * stride) * 30 + lane]);
        }
        float4 o0 = process_row(v0, sclane, vclane, wv, bv, meanc, b1, b2, cA, c3, r1, r2, r1A, b3);
        float4 o1 = process_row(v1, sclane, vclane, wv, bv, meanc, b1, b2, cA, c3, r1, r2, r1A, b3);
        float4 o2 = process_row(v2, sclane, vclane, wv, bv, meanc, b1, b2, cA, c3, r1, r2, r1A, b3);
        float4 o3 = process_row(v3, sclane, vclane, wv, bv, meanc, b1, b2, cA, c3, r1, r2, r1A, b3);
        if (io) {
            __stcs(&out[(long long)row * 30 + lane], o0);
            __stcs(&out[(long long)(row + stride) * 30 + lane], o1);
            __stcs(&out[(long long)(row + 2 * stride) * 30 + lane], o2);
            __stcs(&out[(long long)(row + 3 * stride) * 30 + lane], o3);
        }
        float4 o4 = process_row(v4, sclane, vclane, wv, bv, meanc, b1, b2, cA, c3, r1, r2, r1A, b3);
        float4 o5 = process_row(v5, sclane, vclane, wv, bv, meanc, b1, b2, cA, c3, r1, r2, r1A, b3);
        float4 o6 = process_row(v6, sclane, vclane, wv, bv, meanc, b1, b2, cA, c3, r1, r2, r1A, b3);
        float4 o7 = process_row(v7, sclane, vclane, wv, bv, meanc, b1, b2, cA, c3, r1, r2, r1A, b3);
        if (io) {
            __stcs(&out[(long long)(row + 4 * stride) * 30 + lane], o4);
            __stcs(&out[(long long)(row + 5 * stride) * 30 + lane], o5);
            __stcs(&out[(long long)(row + 6 * stride) * 30 + lane], o6);
            __stcs(&out[(long long)(row + 7 * stride) * 30 + lane], o7);
        }
    }
    for (; row < N; row += stride) {
        float4 v0 = make_float4(0.f, 0.f, 0.f, 0.f);
        if (io) v0 = ldcs4(&x[(long long)row * 30 + lane]);
        float4 o0 = process_row(v0, sclane, vclane, wv, bv, meanc, b1, b2, cA, c3, r1, r2, r1A, b3);
        if (io) __stcs(&out[(long long)row * 30 + lane], o0);
    }
}

extern "C" void kernel_launch(void* const* d_in, const int* in_sizes, int n_in,
                              void* d_out, int out_size) {
    const float* x = (const float*)d_in[0];
    const float* w = (const float*)d_in[1];
    const float* b = (const float*)d_in[2];
    float* out = (float*)d_out;
    const int N = in_sizes[0] / 120;

    k_reduce<<<RB, 256>>>((const float4*)x, N);
    k_finalize<<<1, 768>>>(RB, 1.0f / (float)N);
    k_main<<<MB, 256>>>((const float4*)x, w, b, (float4*)out, N);
}

// round 17
// speedup vs baseline: 1.1900x; 1.0710x over previous
#include <cuda_runtime.h>

// RNAPocketEncoderV3: LayerNorm on first 32 feats + global-mean norm-rescale of
// 16 vec(3) + 8 ten(5) channels. Two passes (global mean couples all rows).
//
// Row = 120 floats = 30 float4.
//   [0,32)   scalar -> layernorm (lanes 0-7)
//   [32,80)  16 vec(3)  -> channels 0..15   (lanes 8..19)
//   [80,120) 8 ten(5)   -> channels 16..23  (lanes 20..29)
//
// Measured-best configuration (131.5us): ascending walk both passes, straight
// 4x unroll with loads batched first, .cs streaming hints, shfl-routed channel
// reduction (no smem atomics). Rejected by measurement: descending walk (R11),
// hand software-pipelining (R13), 8x unroll (R15).

#define NCH 24
#define EPS_LN   1e-5f
#define EPS_NORM 1e-6f
#define EPS2     1e-12f
#define RB 1184
#define MB 4096
#define FULL 0xffffffffu

__device__ float g_partials[RB * NCH];
__device__ float g_mean[NCH];

__device__ __forceinline__ int chan(int e) {   // e in [32,120)
    return (e < 80) ? ((e - 32) / 3) : (16 + (e - 80) / 5);
}

// routing for destination lane c in [0,24): channel c = contrib1 + contrib2
//   contrib1 = (c%4==0 ? sA : sB) from lane r1(c); contrib2 = sA from lane r2(c)
//   (r2=0 -> lane0, whose partials are 0)
__device__ __forceinline__ void routing(int lane, int& r1, int& r2, bool& r1A) {
    r1 = 0; r2 = 0;
    if (lane < 16) {
        r1 = 8 + (3 * lane) / 4;
        int m = lane & 3;
        r2 = (m == 1 || m == 2) ? (r1 + 1) : 0;
    } else if (lane < 24) {
        int j = lane - 16;
        r1 = 20 + (5 * j) / 4;
        r2 = r1 + 1;
    }
    r1A = ((lane & 3) == 0);
}

__device__ __forceinline__ void partials(const float4& v, bool b1, bool b2, bool b3,
                                         float& sA, float& sB) {
    float q0 = v.x * v.x, q1 = v.y * v.y, q2 = v.z * v.z, q3 = v.w * v.w;
    sA = q0; sB = 0.f;
    if (b1) sA += q1; else sB += q1;
    if (b2) sA += q2; else sB += q2;
    if (b3) sA += q3; else sB += q3;
}

__device__ __forceinline__ float chan_sum(float sA, float sB, int r1, int r2, bool r1A) {
    float a1 = __shfl_sync(FULL, sA, r1);
    float b1 = __shfl_sync(FULL, sB, r1);
    float a2 = __shfl_sync(FULL, sA, r2);
    return (r1A ? a1 : b1) + a2;
}

__device__ __forceinline__ float clamped_norm(float n2) {
    return (n2 > EPS2) ? n2 * rsqrtf(n2) : EPS_NORM;
}

__device__ __forceinline__ float4 ldcs4(const float4* p) {
    return __ldcs(p);
}

// -------- Pass 1: per-channel sum of clamped norms (block partials) --------
__global__ __launch_bounds__(256)
void k_reduce(const float4* __restrict__ x, int N) {
    __shared__ float warp_acc[8][NCH];
    const int tid  = threadIdx.x;
    const int wid  = tid >> 5;
    const int lane = tid & 31;

    const int gwarp  = blockIdx.x * 8 + wid;
    const int stride = gridDim.x * 8;
    const bool ldlane = (lane >= 8 && lane < 30);

    bool b1 = true, b2 = true, b3 = true;
    if (ldlane) {
        int e0 = lane * 4, cA = chan(e0);
        b1 = (chan(e0 + 1) == cA); b2 = (chan(e0 + 2) == cA); b3 = (chan(e0 + 3) == cA);
    }
    int r1, r2; bool r1A;
    routing(lane, r1, r2, r1A);

    float acc = 0.f;
    int row = gwarp;
    for (; row + 3 * stride < N; row += 4 * stride) {
        float4 v0, v1, v2, v3;
        v0 = v1 = v2 = v3 = make_float4(0.f, 0.f, 0.f, 0.f);
        if (ldlane) {
            v0 = ldcs4(&x[(long long)row * 30 + lane]);
            v1 = ldcs4(&x[(long long)(row + stride) * 30 + lane]);
            v2 = ldcs4(&x[(long long)(row + 2 * stride) * 30 + lane]);
            v3 = ldcs4(&x[(long long)(row + 3 * stride) * 30 + lane]);
        }
        float sA0, sB0, sA1, sB1, sA2, sB2, sA3, sB3;
        partials(v0, b1, b2, b3, sA0, sB0);
        partials(v1, b1, b2, b3, sA1, sB1);
        partials(v2, b1, b2, b3, sA2, sB2);
        partials(v3, b1, b2, b3, sA3, sB3);
        float n0 = chan_sum(sA0, sB0, r1, r2, r1A);
        float n1 = chan_sum(sA1, sB1, r1, r2, r1A);
        float n2 = chan_sum(sA2, sB2, r1, r2, r1A);
        float n3 = chan_sum(sA3, sB3, r1, r2, r1A);
        acc += clamped_norm(n0) + clamped_norm(n1) + clamped_norm(n2) + clamped_norm(n3);
    }
    for (; row < N; row += stride) {
        float4 v0 = make_float4(0.f, 0.f, 0.f, 0.f);
        if (ldlane) v0 = ldcs4(&x[(long long)row * 30 + lane]);
        float sA, sB;
        partials(v0, b1, b2, b3, sA, sB);
        float n = chan_sum(sA, sB, r1, r2, r1A);
        acc += clamped_norm(n);
    }

    if (lane < NCH) warp_acc[wid][lane] = acc;
    __syncthreads();
    if (tid < NCH) {
        float s = 0.f;
        #pragma unroll
        for (int w = 0; w < 8; w++) s += warp_acc[w][tid];   // fixed order: deterministic
        g_partials[blockIdx.x * NCH + tid] = s;
    }
}

// -------- Pass 1b: finalize means --------
__global__ void k_finalize(int nblocks, float invN) {
    const int wid  = threadIdx.x >> 5;
    const int lane = threadIdx.x & 31;
    if (wid < NCH) {
        float s = 0.f;
        for (int i = lane; i < nblocks; i += 32) s += g_partials[i * NCH + wid];
        #pragma unroll
        for (int o = 16; o; o >>= 1) s += __shfl_xor_sync(FULL, s, o);
        if (lane == 0) g_mean[wid] = s * invN;
    }
}

// -------- Pass 2: layernorm + rescale (4x unrolled, MLP=4) --------
__device__ __forceinline__ float4 process_row(
    const float4& v, bool sclane, bool vclane,
    const float4& wv, const float4& bv, float meanc,
    bool b1, bool b2, int cA, int c3,
    int r1, int r2, bool r1A, bool b3)
{
    float s = 0.f, sq = 0.f;
    if (sclane) {
        s  = v.x + v.y + v.z + v.w;
        sq = v.x * v.x + v.y * v.y + v.z * v.z + v.w * v.w;
    }
    #pragma unroll
    for (int o = 4; o; o >>= 1) {
        s  += __shfl_xor_sync(FULL, s,  o);
        sq += __shfl_xor_sync(FULL, sq, o);
    }

    float sA = 0.f, sB = 0.f;
    if (vclane) partials(v, b1, b2, b3, sA, sB);
    float n2 = chan_sum(sA, sB, r1, r2, r1A);
    float scale = (n2 > EPS2) ? meanc * rsqrtf(n2) : meanc * (1.f / EPS_NORM);

    float sc_lo = __shfl_sync(FULL, scale, cA);
    float sc_hi = __shfl_sync(FULL, scale, c3);

    float4 o4 = make_float4(0.f, 0.f, 0.f, 0.f);
    if (sclane) {
        float mu  = s * (1.f / 32.f);
        float var = sq * (1.f / 32.f) - mu * mu;
        float r   = rsqrtf(var + EPS_LN);
        o4.x = (v.x - mu) * r * wv.x + bv.x;
        o4.y = (v.y - mu) * r * wv.y + bv.y;
        o4.z = (v.z - mu) * r * wv.z + bv.z;
        o4.w = (v.w - mu) * r * wv.w + bv.w;
    } else if (vclane) {
        o4.x = v.x * sc_lo;
        o4.y = v.y * (b1 ? sc_lo : sc_hi);
        o4.z = v.z * (b2 ? sc_lo : sc_hi);
        o4.w = v.w * sc_hi;
    }
    return o4;
}

__global__ __launch_bounds__(256)
void k_main(const float4* __restrict__ x,
            const float* __restrict__ w, const float* __restrict__ b,
            float4* __restrict__ out, int N) {
    const int tid  = threadIdx.x;
    const int wid  = tid >> 5;
    const int lane = tid & 31;

    const int gwarp  = blockIdx.x * 8 + wid;
    const int stride = gridDim.x * 8;
    const bool sclane = (lane < 8);
    const bool vclane = (lane >= 8 && lane < 30);

    float4 wv = make_float4(0.f, 0.f, 0.f, 0.f), bv = wv;
    if (sclane) {
        wv = __ldg(&((const float4*)w)[lane]);
        bv = __ldg(&((const float4*)b)[lane]);
    }
    const float meanc = (lane < NCH) ? g_mean[lane] : 0.f;

    int cA = 0, c3 = 0; bool b1 = true, b2 = true, b3 = true;
    if (vclane) {
        int e0 = lane * 4;
        cA = chan(e0); c3 = chan(e0 + 3);
        b1 = (chan(e0 + 1) == cA); b2 = (chan(e0 + 2) == cA); b3 = (c3 == cA);
    }
    int r1, r2; bool r1A;
    routing(lane, r1, r2, r1A);

    int row = gwarp;
    for (; row + 3 * stride < N; row += 4 * stride) {
        float4 v0, v1, v2, v3;
        v0 = v1 = v2 = v3 = make_float4(0.f, 0.f, 0.f, 0.f);
        if (lane < 30) {
            v0 = ldcs4(&x[(long long)row * 30 + lane]);
            v1 = ldcs4(&x[(long long)(row + stride) * 30 + lane]);
            v2 = ldcs4(&x[(long long)(row + 2 * stride) * 30 + lane]);
            v3 = ldcs4(&x[(long long)(row + 3 * stride) * 30 + lane]);
        }
        float4 o0 = process_row(v0, sclane, vclane, wv, bv, meanc, b1, b2, cA, c3, r1, r2, r1A, b3);
        float4 o1 = process_row(v1, sclane, vclane, wv, bv, meanc, b1, b2, cA, c3, r1, r2, r1A, b3);
        float4 o2 = process_row(v2, sclane, vclane, wv, bv, meanc, b1, b2, cA, c3, r1, r2, r1A, b3);
        float4 o3 = process_row(v3, sclane, vclane, wv, bv, meanc, b1, b2, cA, c3, r1, r2, r1A, b3);
        if (lane < 30) {
            __stcs(&out[(long long)row * 30 + lane], o0);
            __stcs(&out[(long long)(row + stride) * 30 + lane], o1);
            __stcs(&out[(long long)(row + 2 * stride) * 30 + lane], o2);
            __stcs(&out[(long long)(row + 3 * stride) * 30 + lane], o3);
        }
    }
    for (; row < N; row += stride) {
        float4 v0 = make_float4(0.f, 0.f, 0.f, 0.f);
        if (lane < 30) v0 = ldcs4(&x[(long long)row * 30 + lane]);
        float4 o0 = process_row(v0, sclane, vclane, wv, bv, meanc, b1, b2, cA, c3, r1, r2, r1A, b3);
        if (lane < 30) __stcs(&out[(long long)row * 30 + lane], o0);
    }
}

extern "C" void kernel_launch(void* const* d_in, const int* in_sizes, int n_in,
                              void* d_out, int out_size) {
    const float* x = (const float*)d_in[0];
    const float* w = (const float*)d_in[1];
    const float* b = (const float*)d_in[2];
    float* out = (float*)d_out;
    const int N = in_sizes[0] / 120;

    k_reduce<<<RB, 256>>>((const float4*)x, N);
    k_finalize<<<1, 768>>>(RB, 1.0f / (float)N);
    k_main<<<MB, 256>>>((const float4*)x, w, b, (float4*)out, N);
}